// round 2
// baseline (speedup 1.0000x reference)
#include <cuda_runtime.h>

#define B_TOTAL  131072
#define DIM      1024
#define NH       21
#define ROWS     256        // rows per block
#define KC       32         // k-chunk
#define THREADS  128
#define XS_STRIDE 36        // padded row stride (floats) -> conflict-free LDS.128

__global__ __launch_bounds__(THREADS, 2)
void linheads_kernel(const float* __restrict__ x,
                     const float* __restrict__ v_conf,
                     const float* __restrict__ W,
                     const float* __restrict__ bias,
                     float* __restrict__ result,
                     float* __restrict__ out)
{
    __shared__ float xs[ROWS * XS_STRIDE];   // 36864 B
    __shared__ float ws[NH * KC];            // 2688 B
    __shared__ float bs[NH];

    const int t = threadIdx.x;
    const long long row0 = (long long)blockIdx.x * ROWS;

    if (t < NH) bs[t] = bias[t];

    // packed f32x2 accumulators: 2 rows x 21 heads
    unsigned long long acc[2][NH];
#pragma unroll
    for (int r = 0; r < 2; r++)
#pragma unroll
        for (int h = 0; h < NH; h++) acc[r][h] = 0ULL;

    for (int k0 = 0; k0 < DIM; k0 += KC) {
        // --- stage x tile: 256 rows x 32 floats (coalesced float4) ---
#pragma unroll
        for (int it = 0; it < 16; it++) {
            int row = it * 16 + (t >> 3);
            int vec = t & 7;
            float4 v = *(const float4*)&x[(row0 + row) * DIM + k0 + vec * 4];
            *(float4*)&xs[row * XS_STRIDE + vec * 4] = v;
        }
        // --- stage W chunk: 21 x 32 floats = 168 float4 ---
#pragma unroll
        for (int it = 0; it < 2; it++) {
            int m = it * THREADS + t;
            if (m < NH * 8) {
                int h = m >> 3, vec = m & 7;
                float4 v = *(const float4*)&W[(long long)h * DIM + k0 + vec * 4];
                *(float4*)&ws[h * KC + vec * 4] = v;
            }
        }
        __syncthreads();

        // --- compute: thread t owns rows t and t+128 ---
#pragma unroll
        for (int kk = 0; kk < 8; kk++) {
            ulonglong2 xa = *(const ulonglong2*)&xs[t * XS_STRIDE + kk * 4];
            ulonglong2 xb = *(const ulonglong2*)&xs[(t + THREADS) * XS_STRIDE + kk * 4];
#pragma unroll
            for (int h = 0; h < NH; h++) {
                ulonglong2 w = *(const ulonglong2*)&ws[h * KC + kk * 4];
                asm("fma.rn.f32x2 %0, %1, %2, %0;" : "+l"(acc[0][h]) : "l"(xa.x), "l"(w.x));
                asm("fma.rn.f32x2 %0, %1, %2, %0;" : "+l"(acc[0][h]) : "l"(xa.y), "l"(w.y));
                asm("fma.rn.f32x2 %0, %1, %2, %0;" : "+l"(acc[1][h]) : "l"(xb.x), "l"(w.x));
                asm("fma.rn.f32x2 %0, %1, %2, %0;" : "+l"(acc[1][h]) : "l"(xb.y), "l"(w.y));
            }
        }
        __syncthreads();
    }

    // --- epilogue: out = dot + bias; result = sum(out * v_conf) ---
#pragma unroll
    for (int r = 0; r < 2; r++) {
        long long row = row0 + t + r * THREADS;
        float res = 0.f;
#pragma unroll
        for (int h = 0; h < NH; h++) {
            float lo = __uint_as_float((unsigned)(acc[r][h] & 0xffffffffULL));
            float hi = __uint_as_float((unsigned)(acc[r][h] >> 32));
            float o = lo + hi + bs[h];
            out[row * NH + h] = o;
            res += o * v_conf[row * NH + h];
        }
        result[row] = res;
    }
}

extern "C" void kernel_launch(void* const* d_in, const int* in_sizes, int n_in,
                              void* d_out, int out_size)
{
    const float* x      = (const float*)d_in[0];   // [B, DIM]
    const float* v_conf = (const float*)d_in[1];   // [B, NH]
    const float* W      = (const float*)d_in[2];   // [NH, DIM]
    const float* bias   = (const float*)d_in[3];   // [NH]

    float* result = (float*)d_out;                 // [B]
    float* out    = (float*)d_out + B_TOTAL;       // [B, NH]

    dim3 grid(B_TOTAL / ROWS);
    linheads_kernel<<<grid, THREADS>>>(x, v_conf, W, bias, result, out);
}

// round 3
// speedup vs baseline: 1.3107x; 1.3107x over previous
#include <cuda_runtime.h>
#include <cstdint>

#define B_TOTAL  131072
#define DIM      1024
#define NH       21
#define ROWS     256
#define KC       32
#define THREADS  256
#define XSTR     36          // padded row stride (floats): conflict-free LDS.128
#define NSTAGE   (DIM / KC)  // 32 k-chunks

__device__ __forceinline__ void cp_async16(uint32_t dst, const void* src) {
    asm volatile("cp.async.cg.shared.global [%0], [%1], 16;\n" :: "r"(dst), "l"(src));
}
__device__ __forceinline__ void cp_commit() {
    asm volatile("cp.async.commit_group;\n" ::: "memory");
}
template<int N> __device__ __forceinline__ void cp_wait() {
    asm volatile("cp.async.wait_group %0;\n" :: "n"(N) : "memory");
}

__global__ __launch_bounds__(THREADS, 2)
void linheads_kernel(const float* __restrict__ x,
                     const float* __restrict__ v_conf,
                     const float* __restrict__ W,
                     const float* __restrict__ bias,
                     float* __restrict__ result,
                     float* __restrict__ out)
{
    __shared__ float xs[2][ROWS * XSTR];   // 2 x 36864 B
    __shared__ float ws[2][NH * KC];       // 2 x 2688 B
    __shared__ float bs[NH];

    const int t = threadIdx.x;
    const long long row0 = (long long)blockIdx.x * ROWS;

    if (t < NH) bs[t] = bias[t];

    // 21 packed f32x2 accumulators (1 row per thread)
    unsigned long long acc[NH];
#pragma unroll
    for (int h = 0; h < NH; h++) acc[h] = 0ULL;

    const uint32_t xs0 = (uint32_t)__cvta_generic_to_shared(&xs[0][0]);
    const uint32_t xs1 = (uint32_t)__cvta_generic_to_shared(&xs[1][0]);
    const uint32_t ws0 = (uint32_t)__cvta_generic_to_shared(&ws[0][0]);
    const uint32_t ws1 = (uint32_t)__cvta_generic_to_shared(&ws[1][0]);

    // ---- stage loader: 256 rows x 32 floats of x, 21 x 32 floats of W ----
    auto load_stage = [&](int k0, int buf) {
        uint32_t xb = buf ? xs1 : xs0;
        uint32_t wb = buf ? ws1 : ws0;
#pragma unroll
        for (int i = 0; i < 8; i++) {
            int m   = i * THREADS + t;        // 0..2047 float4 slots
            int row = m >> 3;
            int vec = m & 7;
            cp_async16(xb + (uint32_t)(row * XSTR + vec * 4) * 4,
                       &x[(row0 + row) * DIM + k0 + vec * 4]);
        }
        if (t < NH * 8) {                     // 168 float4 slots
            int h = t >> 3, vec = t & 7;
            cp_async16(wb + (uint32_t)(h * KC + vec * 4) * 4,
                       &W[(long long)h * DIM + k0 + vec * 4]);
        }
        cp_commit();
    };

    load_stage(0, 0);

    for (int s = 0; s < NSTAGE; s++) {
        const int buf = s & 1;
        if (s + 1 < NSTAGE) {
            load_stage((s + 1) * KC, buf ^ 1);
            cp_wait<1>();
        } else {
            cp_wait<0>();
        }
        __syncthreads();

        // ---- compute this chunk: 8 steps of 4 k-values ----
#pragma unroll
        for (int kk = 0; kk < 8; kk++) {
            ulonglong2 xv = *(const ulonglong2*)&xs[buf][t * XSTR + kk * 4];
#pragma unroll
            for (int h = 0; h < NH; h++) {
                ulonglong2 w = *(const ulonglong2*)&ws[buf][h * KC + kk * 4];
                asm("fma.rn.f32x2 %0, %1, %2, %0;" : "+l"(acc[h]) : "l"(xv.x), "l"(w.x));
                asm("fma.rn.f32x2 %0, %1, %2, %0;" : "+l"(acc[h]) : "l"(xv.y), "l"(w.y));
            }
        }
        __syncthreads();
    }

    // ---- epilogue ----
    const long long row = row0 + t;
    float res = 0.f;
#pragma unroll
    for (int h = 0; h < NH; h++) {
        float lo = __uint_as_float((unsigned)(acc[h] & 0xffffffffULL));
        float hi = __uint_as_float((unsigned)(acc[h] >> 32));
        float o  = lo + hi + bs[h];
        out[row * NH + h] = o;
        res += o * v_conf[row * NH + h];
    }
    result[row] = res;
}

extern "C" void kernel_launch(void* const* d_in, const int* in_sizes, int n_in,
                              void* d_out, int out_size)
{
    const float* x      = (const float*)d_in[0];   // [B, DIM]
    const float* v_conf = (const float*)d_in[1];   // [B, NH]
    const float* W      = (const float*)d_in[2];   // [NH, DIM]
    const float* bias   = (const float*)d_in[3];   // [NH]

    float* result = (float*)d_out;                 // [B]
    float* out    = (float*)d_out + B_TOTAL;       // [B, NH]

    dim3 grid(B_TOTAL / ROWS);
    linheads_kernel<<<grid, THREADS>>>(x, v_conf, W, bias, result, out);
}